// round 14
// baseline (speedup 1.0000x reference)
#include <cuda_runtime.h>
#include <cuda_bf16.h>
#include <cstdint>

#define BDIM 8
#define CDIM 256
#define NDIM 4096
#define BT   128
#define KB   16

// ---------------- device scratch (allocation-free rule) ----------------
__device__ __align__(1024) float g_MT[CDIM * CDIM];                         // MT[k][c]
__device__ __align__(1024) __nv_bfloat16 g_Yhi[(size_t)BDIM * NDIM * CDIM]; // Yt hi: [b][m][c]
__device__ __align__(1024) __nv_bfloat16 g_Ylo[(size_t)BDIM * NDIM * CDIM]; // Yt lo
__device__ __align__(1024) __nv_bfloat16 g_Xhi[(size_t)BDIM * NDIM * CDIM]; // Xt hi: [b][n][c]
__device__ __align__(1024) __nv_bfloat16 g_Xlo[(size_t)BDIM * NDIM * CDIM]; // Xt lo
// B in mma-fragment order: [b][p = mt*16+kc][comp][lane] -> uint2 (b0,b1)
__device__ __align__(1024) uint2 g_Bp[(size_t)BDIM * 8192 * 2 * 32];        // 33.5 MB

// ---------------- helpers ----------------
__device__ __forceinline__ void cp16(uint32_t s, const void* g) {
    asm volatile("cp.async.cg.shared.global [%0], [%1], 16;" :: "r"(s), "l"(g));
}
__device__ __forceinline__ void cp_commit() { asm volatile("cp.async.commit_group;"); }
__device__ __forceinline__ void cp_wait0()  { asm volatile("cp.async.wait_group 0;"); }
__device__ __forceinline__ void cp_wait1()  { asm volatile("cp.async.wait_group 1;"); }

__device__ __forceinline__ unsigned long long dup2(float x) {
    unsigned long long r;
    asm("mov.b64 %0, {%1, %1};" : "=l"(r) : "f"(x));
    return r;
}
__device__ __forceinline__ void ffma2(unsigned long long& d, unsigned long long a, unsigned long long b) {
    asm("fma.rn.f32x2 %0, %1, %2, %0;" : "+l"(d) : "l"(a), "l"(b));
}
__device__ __forceinline__ float lo32(unsigned long long v) { return __uint_as_float((unsigned int)v); }
__device__ __forceinline__ float hi32(unsigned long long v) { return __uint_as_float((unsigned int)(v >> 32)); }

__device__ __forceinline__ unsigned short f2bf(float x) {
    return __bfloat16_as_ushort(__float2bfloat16(x));
}
__device__ __forceinline__ float bf2f(unsigned short u) {
    __nv_bfloat16_raw r; r.x = u;
    return __bfloat162float(__nv_bfloat16(r));
}
__device__ __forceinline__ uint32_t smem_u32(const void* p) {
    uint32_t a;
    asm("{ .reg .u64 t; cvta.to.shared.u64 t, %1; cvt.u32.u64 %0, t; }" : "=r"(a) : "l"(p));
    return a;
}

// ---------------- tensor-core primitives (plain sm_103-safe: sm_80 era) ----------------
__device__ __forceinline__ void ldsm4(uint32_t* r, uint32_t addr) {
    asm volatile("ldmatrix.sync.aligned.m8n8.x4.shared.b16 {%0,%1,%2,%3}, [%4];"
        : "=r"(r[0]), "=r"(r[1]), "=r"(r[2]), "=r"(r[3]) : "r"(addr));
}
__device__ __forceinline__ void mma_bf16(float* d, const uint32_t* a, const uint32_t* b) {
    asm volatile("mma.sync.aligned.m16n8k16.row.col.f32.bf16.bf16.f32 "
        "{%0,%1,%2,%3}, {%4,%5,%6,%7}, {%8,%9}, {%0,%1,%2,%3};"
        : "+f"(d[0]), "+f"(d[1]), "+f"(d[2]), "+f"(d[3])
        : "r"(a[0]), "r"(a[1]), "r"(a[2]), "r"(a[3]), "r"(b[0]), "r"(b[1]));
}

// ---------------- kernel A: MT fold ----------------
__global__ void mt_kernel(const float* __restrict__ Wq, const float* __restrict__ Wk) {
    __shared__ float Qs[16][16];
    __shared__ float Ks[16][16];
    const int tx = threadIdx.x, ty = threadIdx.y;
    const int c = blockIdx.x * 16 + tx;
    const int k = blockIdx.y * 16 + ty;
    float acc = 0.f;
    for (int d0 = 0; d0 < CDIM; d0 += 16) {
        Qs[ty][tx] = Wq[(d0 + ty) * CDIM + blockIdx.x * 16 + tx];
        Ks[ty][tx] = Wk[(d0 + ty) * CDIM + blockIdx.y * 16 + tx];
        __syncthreads();
#pragma unroll
        for (int dd = 0; dd < 16; dd++) acc += Qs[dd][tx] * Ks[dd][ty];
        __syncthreads();
    }
    g_MT[k * CDIM + c] = acc;
}

// ---------------- kernel A2: Xt split transpose ----------------
__global__ void xt_kernel(const float* __restrict__ X) {
    __shared__ float s[32][33];
    const int b = blockIdx.z;
    const int n0 = blockIdx.x * 32, c0 = blockIdx.y * 32;
    const float* Xb = X + (size_t)b * CDIM * NDIM;
    const int tx = threadIdx.x, ty = threadIdx.y;
#pragma unroll
    for (int i = 0; i < 4; i++)
        s[ty + 8 * i][tx] = Xb[(size_t)(c0 + ty + 8 * i) * NDIM + n0 + tx];
    __syncthreads();
#pragma unroll
    for (int i = 0; i < 4; i++) {
        float v = s[tx][ty + 8 * i];
        unsigned short h = f2bf(v);
        unsigned short l = f2bf(v - bf2f(h));
        size_t off = ((size_t)b * NDIM + n0 + ty + 8 * i) * CDIM + c0 + tx;
        ((unsigned short*)g_Xhi)[off] = h;
        ((unsigned short*)g_Xlo)[off] = l;
    }
}

// ---------------- kernel B: Y = M X, written TRANSPOSED as bf16 hi/lo splits ----------------
__global__ __launch_bounds__(256, 2) void ymat_kernel(const float* __restrict__ X) {
    const int b  = blockIdx.z;
    const int m0 = blockIdx.x * BT;
    const int c0 = blockIdx.y * BT;
    const float* Xb = X + (size_t)b * CDIM * NDIM;

    __shared__ float As[2][KB][BT];
    __shared__ float Bs[2][KB][BT];

    const int tid = threadIdx.x;
    const int tx = tid & 15, ty = tid >> 4;
    const int kk0 = tid >> 5;
    const int c4 = (tid & 31) * 4;

    uint32_t aAddr0 = (uint32_t)__cvta_generic_to_shared(&As[0][kk0][c4]);
    uint32_t bAddr0 = (uint32_t)__cvta_generic_to_shared(&Bs[0][kk0][c4]);
    const uint32_t bufStride = (uint32_t)(KB * BT * 4);
    const uint32_t rowOff = 8 * BT * 4;

    const float* gA0 = g_MT + kk0 * CDIM + c0 + c4;
    const float* gB0 = Xb + kk0 * NDIM + m0 + c4;

    cp16(aAddr0, gA0);
    cp16(aAddr0 + rowOff, gA0 + 8 * CDIM);
    cp16(bAddr0, gB0);
    cp16(bAddr0 + rowOff, gB0 + 8 * NDIM);
    cp_commit();

    unsigned long long acc[8][4];
#pragma unroll
    for (int i = 0; i < 8; i++)
#pragma unroll
        for (int j = 0; j < 4; j++) acc[i][j] = 0ull;

    const int NKC = CDIM / KB;
#pragma unroll 1
    for (int kc = 0; kc < NKC; kc++) {
        if (kc + 1 < NKC) {
            uint32_t boff = (uint32_t)((kc + 1) & 1) * bufStride;
            const float* ga = gA0 + (kc + 1) * KB * CDIM;
            const float* gb = gB0 + (kc + 1) * KB * NDIM;
            cp16(aAddr0 + boff, ga);
            cp16(aAddr0 + boff + rowOff, ga + 8 * CDIM);
            cp16(bAddr0 + boff, gb);
            cp16(bAddr0 + boff + rowOff, gb + 8 * NDIM);
            cp_commit();
            cp_wait1();
        } else {
            cp_wait0();
        }
        __syncthreads();
        const float (*Ac)[BT] = As[kc & 1];
        const float (*Bc)[BT] = Bs[kc & 1];
#pragma unroll
        for (int kk = 0; kk < KB; kk++) {
            float4 a0 = *(const float4*)&Ac[kk][ty * 8];
            float4 a1 = *(const float4*)&Ac[kk][ty * 8 + 4];
            ulonglong2 b0 = *(const ulonglong2*)&Bc[kk][tx * 8];
            ulonglong2 b1 = *(const ulonglong2*)&Bc[kk][tx * 8 + 4];
            unsigned long long bp0 = b0.x, bp1 = b0.y, bp2 = b1.x, bp3 = b1.y;
            float av[8] = {a0.x, a0.y, a0.z, a0.w, a1.x, a1.y, a1.z, a1.w};
#pragma unroll
            for (int i = 0; i < 8; i++) {
                unsigned long long ai = dup2(av[i]);
                ffma2(acc[i][0], ai, bp0);
                ffma2(acc[i][1], ai, bp1);
                ffma2(acc[i][2], ai, bp2);
                ffma2(acc[i][3], ai, bp3);
            }
        }
        __syncthreads();
    }

    // Transposed split write: Yt[b][m][c] hi/lo bf16.
#pragma unroll
    for (int jj = 0; jj < 8; jj++) {
        uint32_t hw[4], lw[4];
#pragma unroll
        for (int p = 0; p < 4; p++) {
            float v0 = (jj & 1) ? hi32(acc[2 * p][jj >> 1])     : lo32(acc[2 * p][jj >> 1]);
            float v1 = (jj & 1) ? hi32(acc[2 * p + 1][jj >> 1]) : lo32(acc[2 * p + 1][jj >> 1]);
            unsigned short h0 = f2bf(v0), h1 = f2bf(v1);
            unsigned short l0 = f2bf(v0 - bf2f(h0)), l1 = f2bf(v1 - bf2f(h1));
            hw[p] = (uint32_t)h0 | ((uint32_t)h1 << 16);
            lw[p] = (uint32_t)l0 | ((uint32_t)l1 << 16);
        }
        size_t row = (size_t)b * NDIM + (m0 + tx * 8 + jj);
        uint4* dh = (uint4*)(g_Yhi + row * CDIM + c0 + ty * 8);
        uint4* dl = (uint4*)(g_Ylo + row * CDIM + c0 + ty * 8);
        *dh = make_uint4(hw[0], hw[1], hw[2], hw[3]);
        *dl = make_uint4(lw[0], lw[1], lw[2], lw[3]);
    }
}

// ---------------- kernel B2: repack Yt rows -> mma B fragments ----------------
// g_Bp[((b*8192 + p)*2 + comp)*32 + L], p = mt*16 + kc:
//   b0 = Yt[m = mt*8 + L/4][k = kc*16 + 2(L%4) + {0,1}]  (bf16x2)
//   b1 = same with k+8
__global__ void bpack_kernel() {
    const int b = blockIdx.y;
    const int w = threadIdx.x >> 5;
    const int L = threadIdx.x & 31;
    const int p = blockIdx.x * 8 + w;       // 0..8191
    const int mt = p >> 4, kc = p & 15;
    const int m = mt * 8 + (L >> 2);
    const int k0 = kc * 16 + 2 * (L & 3);

    const unsigned short* yh = (const unsigned short*)g_Yhi + ((size_t)b * NDIM + m) * CDIM;
    const unsigned short* yl = (const unsigned short*)g_Ylo + ((size_t)b * NDIM + m) * CDIM;
    uint32_t h0 = *(const uint32_t*)(yh + k0);
    uint32_t h1 = *(const uint32_t*)(yh + k0 + 8);
    uint32_t l0 = *(const uint32_t*)(yl + k0);
    uint32_t l1 = *(const uint32_t*)(yl + k0 + 8);
    size_t base = (((size_t)b * 8192 + p) * 2) * 32 + L;
    g_Bp[base]      = make_uint2(h0, h1);
    g_Bp[base + 32] = make_uint2(l0, l1);
}

// ---------------- kernel C: mma.sync flash row-stats, B direct from gmem fragments ----------------
// SMEM: Ahi[128][512B] @0 (64KB), Alo @65536 (64KB), sdiag @131072, sfac @131584. Total 132096.
#define SM_ALO   65536u
#define SM_SDIAG 131072u
#define SM_SFAC  131584u
#define SMEM_SZ  132096

__device__ __forceinline__ uint32_t a_addr(uint32_t sb, int comp, int row, int kc, int L) {
    int r = row + (L & 15);
    int kh = (L >> 4) & 1;
    return sb + (uint32_t)comp * SM_ALO + (uint32_t)(r * 512 + ((kc ^ (r & 7)) * 32) + kh * 16);
}

__global__ __launch_bounds__(128, 1) void attn_kernel(const float* __restrict__ X,
                                                      float* __restrict__ out) {
    extern __shared__ __align__(1024) char smem[];
    const uint32_t sb = smem_u32(smem);
    const int tid = threadIdx.x;
    const int L = tid & 31;
    const int w = tid >> 5;           // 0..3, all compute
    const int b  = blockIdx.y;
    const int n0 = blockIdx.x * 128;

    const float* Xb = X + (size_t)b * CDIM * NDIM;
    float* sdiag = (float*)(smem + SM_SDIAG);
    float* sfac  = (float*)(smem + SM_SFAC);

    // ---- prologue: stage A (Xt hi/lo) into swizzled smem (one time) ----
    for (int i = tid; i < 8192; i += 128) {
        int comp = i >> 12;
        int rem = i & 4095;
        int r = rem >> 5, u = rem & 31;
        const __nv_bfloat16* src =
            (comp ? g_Xlo : g_Xhi) + ((size_t)b * NDIM + n0 + r) * CDIM + u * 8;
        uint32_t dst = sb + (uint32_t)comp * SM_ALO +
                       (uint32_t)(r * 512 + (((u >> 1) ^ (r & 7)) * 32) + (u & 1) * 16);
        cp16(dst, src);
    }
    cp_commit();
    cp_wait0();
    __syncthreads();

    // ---- mainloop: warps fully independent, no barriers ----
    const int NIT = NDIM / 32;          // 128
    const int diag_it = blockIdx.x * 4 + w;
    const uint2* BpL = g_Bp + (size_t)b * 8192 * 2 * 32 + L;

    float mrun[4], srun[4];
#pragma unroll
    for (int j = 0; j < 4; j++) { mrun[j] = -1e30f; srun[j] = 0.f; }

#pragma unroll 1
    for (int it = 0; it < NIT; it++) {
        float acc[2][4][4];
#pragma unroll
        for (int a = 0; a < 2; a++)
#pragma unroll
            for (int bt = 0; bt < 4; bt++)
#pragma unroll
                for (int q = 0; q < 4; q++) acc[a][bt][q] = 0.f;

#pragma unroll 4
        for (int kc = 0; kc < 16; kc++) {
            // B fragments straight from gmem (fragment-packed, coalesced LDG.64)
            uint2 BH[4], BL[4];
#pragma unroll
            for (int bt = 0; bt < 4; bt++) {
                size_t off = (size_t)(((it * 4 + bt) * 16 + kc) * 2) * 32;
                BH[bt] = BpL[off];
                BL[bt] = BpL[off + 32];
            }
            // A fragments via ldmatrix from smem
            uint32_t AH[2][4], AL[2][4];
            ldsm4(AH[0], a_addr(sb, 0, w * 32,      kc, L));
            ldsm4(AH[1], a_addr(sb, 0, w * 32 + 16, kc, L));
            ldsm4(AL[0], a_addr(sb, 1, w * 32,      kc, L));
            ldsm4(AL[1], a_addr(sb, 1, w * 32 + 16, kc, L));
            // 3 chains: hi*hi + hi*lo + lo*hi
#pragma unroll
            for (int a = 0; a < 2; a++)
#pragma unroll
                for (int bt = 0; bt < 4; bt++)
                    mma_bf16(acc[a][bt], AH[a], (const uint32_t*)&BH[bt]);
#pragma unroll
            for (int a = 0; a < 2; a++)
#pragma unroll
                for (int bt = 0; bt < 4; bt++)
                    mma_bf16(acc[a][bt], AH[a], (const uint32_t*)&BL[bt]);
#pragma unroll
            for (int a = 0; a < 2; a++)
#pragma unroll
                for (int bt = 0; bt < 4; bt++)
                    mma_bf16(acc[a][bt], AL[a], (const uint32_t*)&BH[bt]);
        }

        // ---- diag extraction when this m-tile covers this warp's rows ----
        if (it == diag_it && ((L >> 3) == (L & 3))) {
            int r7 = L >> 2;
#pragma unroll
            for (int a = 0; a < 2; a++)
#pragma unroll
                for (int h = 0; h < 2; h++)
                    sdiag[w * 32 + 16 * a + 8 * h + r7] = acc[a][2 * a + h][2 * h + (r7 & 1)];
        }

        // ---- online softmax: 4 rows x 8 cols per lane ----
#pragma unroll
        for (int a = 0; a < 2; a++)
#pragma unroll
            for (int h = 0; h < 2; h++) {
                const int j = 2 * a + h;
                float v[8];
#pragma unroll
                for (int bt = 0; bt < 4; bt++) {
                    v[2 * bt]     = acc[a][bt][2 * h];
                    v[2 * bt + 1] = acc[a][bt][2 * h + 1];
                }
                float mx = fmaxf(fmaxf(fmaxf(v[0], v[1]), fmaxf(v[2], v[3])),
                                 fmaxf(fmaxf(v[4], v[5]), fmaxf(v[6], v[7])));
                float mnew = fmaxf(mrun[j], mx);
                float ss = __expf(v[0] - mnew) + __expf(v[1] - mnew) +
                           __expf(v[2] - mnew) + __expf(v[3] - mnew) +
                           __expf(v[4] - mnew) + __expf(v[5] - mnew) +
                           __expf(v[6] - mnew) + __expf(v[7] - mnew);
                srun[j] = srun[j] * __expf(mrun[j] - mnew) + ss;
                mrun[j] = mnew;
            }
    }

    // ---- merge across the 4 lanes sharing each row; write sfac ----
#pragma unroll
    for (int j = 0; j < 4; j++) {
        const int a = j >> 1, h = j & 1;
        float m = mrun[j], sv = srun[j];
#pragma unroll
        for (int d = 1; d < 4; d <<= 1) {
            float mo = __shfl_xor_sync(0xffffffffu, m, d);
            float so = __shfl_xor_sync(0xffffffffu, sv, d);
            float mn = fmaxf(m, mo);
            sv = sv * __expf(m - mn) + so * __expf(mo - mn);
            m = mn;
        }
        if ((L & 3) == 0) {
            int nl = w * 32 + 16 * a + 8 * h + (L >> 2);
            sfac[nl] = __expf(sdiag[nl] - m) / sv;
        }
    }
    __syncthreads();

    // ---- store: out[c][n] = X[c][n] * fac[n] ----
    float* Ob = out + (size_t)b * CDIM * NDIM;
#pragma unroll 1
    for (int idx = tid; idx < 256 * 32; idx += 128) {
        int c = idx >> 5, g = idx & 31;
        float4 f = *(const float4*)&sfac[g * 4];
        float4 x = *(const float4*)(Xb + (size_t)c * NDIM + n0 + g * 4);
        x.x *= f.x; x.y *= f.y; x.z *= f.z; x.w *= f.w;
        *(float4*)(Ob + (size_t)c * NDIM + n0 + g * 4) = x;
    }
}

// ---------------- launch ----------------
extern "C" void kernel_launch(void* const* d_in, const int* in_sizes, int n_in,
                              void* d_out, int out_size) {
    const float* pts = (const float*)d_in[0];
    const float* Wq  = (const float*)d_in[1];
    const float* Wk  = (const float*)d_in[2];
    float* out = (float*)d_out;

    cudaFuncSetAttribute(attn_kernel, cudaFuncAttributeMaxDynamicSharedMemorySize, SMEM_SZ);

    mt_kernel<<<dim3(16, 16), dim3(16, 16)>>>(Wq, Wk);
    xt_kernel<<<dim3(NDIM / 32, CDIM / 32, BDIM), dim3(32, 8)>>>(pts);
    ymat_kernel<<<dim3(NDIM / BT, CDIM / BT, BDIM), 256>>>(pts);
    bpack_kernel<<<dim3(1024, BDIM), 256>>>();
    attn_kernel<<<dim3(NDIM / 128, BDIM), 128, SMEM_SZ>>>(pts, out);
}

// round 16
// speedup vs baseline: 1.0729x; 1.0729x over previous
#include <cuda_runtime.h>
#include <cuda_bf16.h>
#include <cstdint>

#define BDIM 8
#define CDIM 256
#define NDIM 4096
#define BT   128
#define KB   16

// ---------------- device scratch (allocation-free rule) ----------------
__device__ __align__(1024) float g_MT[CDIM * CDIM];                         // MT[k][c]
__device__ __align__(1024) __nv_bfloat16 g_Yhi[(size_t)BDIM * NDIM * CDIM]; // Yt hi: [b][m][c]
__device__ __align__(1024) __nv_bfloat16 g_Ylo[(size_t)BDIM * NDIM * CDIM]; // Yt lo
__device__ __align__(1024) __nv_bfloat16 g_Xhi[(size_t)BDIM * NDIM * CDIM]; // Xt hi: [b][n][c]
__device__ __align__(1024) __nv_bfloat16 g_Xlo[(size_t)BDIM * NDIM * CDIM]; // Xt lo

// ---------------- helpers ----------------
__device__ __forceinline__ void cp16(uint32_t s, const void* g) {
    asm volatile("cp.async.cg.shared.global [%0], [%1], 16;" :: "r"(s), "l"(g));
}
__device__ __forceinline__ void cp_commit() { asm volatile("cp.async.commit_group;"); }
__device__ __forceinline__ void cp_wait0()  { asm volatile("cp.async.wait_group 0;"); }
__device__ __forceinline__ void cp_wait1()  { asm volatile("cp.async.wait_group 1;"); }

__device__ __forceinline__ unsigned long long dup2(float x) {
    unsigned long long r;
    asm("mov.b64 %0, {%1, %1};" : "=l"(r) : "f"(x));
    return r;
}
__device__ __forceinline__ void ffma2(unsigned long long& d, unsigned long long a, unsigned long long b) {
    asm("fma.rn.f32x2 %0, %1, %2, %0;" : "+l"(d) : "l"(a), "l"(b));
}
__device__ __forceinline__ float lo32(unsigned long long v) { return __uint_as_float((unsigned int)v); }
__device__ __forceinline__ float hi32(unsigned long long v) { return __uint_as_float((unsigned int)(v >> 32)); }

__device__ __forceinline__ unsigned short f2bf(float x) {
    return __bfloat16_as_ushort(__float2bfloat16(x));
}
__device__ __forceinline__ float bf2f(unsigned short u) {
    __nv_bfloat16_raw r; r.x = u;
    return __bfloat162float(__nv_bfloat16(r));
}
__device__ __forceinline__ uint32_t smem_u32(const void* p) {
    uint32_t a;
    asm("{ .reg .u64 t; cvta.to.shared.u64 t, %1; cvt.u32.u64 %0, t; }" : "=r"(a) : "l"(p));
    return a;
}

// ---------------- tensor-core primitives (plain sm_103-safe: sm_80 era) ----------------
__device__ __forceinline__ void ldsm4(uint32_t* r, uint32_t addr) {
    asm volatile("ldmatrix.sync.aligned.m8n8.x4.shared.b16 {%0,%1,%2,%3}, [%4];"
        : "=r"(r[0]), "=r"(r[1]), "=r"(r[2]), "=r"(r[3]) : "r"(addr));
}
__device__ __forceinline__ void mma_bf16(float* d, const uint32_t* a, const uint32_t* b) {
    asm volatile("mma.sync.aligned.m16n8k16.row.col.f32.bf16.bf16.f32 "
        "{%0,%1,%2,%3}, {%4,%5,%6,%7}, {%8,%9}, {%0,%1,%2,%3};"
        : "+f"(d[0]), "+f"(d[1]), "+f"(d[2]), "+f"(d[3])
        : "r"(a[0]), "r"(a[1]), "r"(a[2]), "r"(a[3]), "r"(b[0]), "r"(b[1]));
}

// ---------------- kernel A: MT fold ----------------
__global__ void mt_kernel(const float* __restrict__ Wq, const float* __restrict__ Wk) {
    __shared__ float Qs[16][16];
    __shared__ float Ks[16][16];
    const int tx = threadIdx.x, ty = threadIdx.y;
    const int c = blockIdx.x * 16 + tx;
    const int k = blockIdx.y * 16 + ty;
    float acc = 0.f;
    for (int d0 = 0; d0 < CDIM; d0 += 16) {
        Qs[ty][tx] = Wq[(d0 + ty) * CDIM + blockIdx.x * 16 + tx];
        Ks[ty][tx] = Wk[(d0 + ty) * CDIM + blockIdx.y * 16 + tx];
        __syncthreads();
#pragma unroll
        for (int dd = 0; dd < 16; dd++) acc += Qs[dd][tx] * Ks[dd][ty];
        __syncthreads();
    }
    g_MT[k * CDIM + c] = acc;
}

// ---------------- kernel A2: Xt split transpose ----------------
__global__ void xt_kernel(const float* __restrict__ X) {
    __shared__ float s[32][33];
    const int b = blockIdx.z;
    const int n0 = blockIdx.x * 32, c0 = blockIdx.y * 32;
    const float* Xb = X + (size_t)b * CDIM * NDIM;
    const int tx = threadIdx.x, ty = threadIdx.y;
#pragma unroll
    for (int i = 0; i < 4; i++)
        s[ty + 8 * i][tx] = Xb[(size_t)(c0 + ty + 8 * i) * NDIM + n0 + tx];
    __syncthreads();
#pragma unroll
    for (int i = 0; i < 4; i++) {
        float v = s[tx][ty + 8 * i];
        unsigned short h = f2bf(v);
        unsigned short l = f2bf(v - bf2f(h));
        size_t off = ((size_t)b * NDIM + n0 + ty + 8 * i) * CDIM + c0 + tx;
        ((unsigned short*)g_Xhi)[off] = h;
        ((unsigned short*)g_Xlo)[off] = l;
    }
}

// ---------------- kernel B: Y = M X, written TRANSPOSED as bf16 hi/lo splits ----------------
__global__ __launch_bounds__(256, 2) void ymat_kernel(const float* __restrict__ X) {
    const int b  = blockIdx.z;
    const int m0 = blockIdx.x * BT;
    const int c0 = blockIdx.y * BT;
    const float* Xb = X + (size_t)b * CDIM * NDIM;

    __shared__ float As[2][KB][BT];
    __shared__ float Bs[2][KB][BT];

    const int tid = threadIdx.x;
    const int tx = tid & 15, ty = tid >> 4;
    const int kk0 = tid >> 5;
    const int c4 = (tid & 31) * 4;

    uint32_t aAddr0 = (uint32_t)__cvta_generic_to_shared(&As[0][kk0][c4]);
    uint32_t bAddr0 = (uint32_t)__cvta_generic_to_shared(&Bs[0][kk0][c4]);
    const uint32_t bufStride = (uint32_t)(KB * BT * 4);
    const uint32_t rowOff = 8 * BT * 4;

    const float* gA0 = g_MT + kk0 * CDIM + c0 + c4;
    const float* gB0 = Xb + kk0 * NDIM + m0 + c4;

    cp16(aAddr0, gA0);
    cp16(aAddr0 + rowOff, gA0 + 8 * CDIM);
    cp16(bAddr0, gB0);
    cp16(bAddr0 + rowOff, gB0 + 8 * NDIM);
    cp_commit();

    unsigned long long acc[8][4];
#pragma unroll
    for (int i = 0; i < 8; i++)
#pragma unroll
        for (int j = 0; j < 4; j++) acc[i][j] = 0ull;

    const int NKC = CDIM / KB;
#pragma unroll 1
    for (int kc = 0; kc < NKC; kc++) {
        if (kc + 1 < NKC) {
            uint32_t boff = (uint32_t)((kc + 1) & 1) * bufStride;
            const float* ga = gA0 + (kc + 1) * KB * CDIM;
            const float* gb = gB0 + (kc + 1) * KB * NDIM;
            cp16(aAddr0 + boff, ga);
            cp16(aAddr0 + boff + rowOff, ga + 8 * CDIM);
            cp16(bAddr0 + boff, gb);
            cp16(bAddr0 + boff + rowOff, gb + 8 * NDIM);
            cp_commit();
            cp_wait1();
        } else {
            cp_wait0();
        }
        __syncthreads();
        const float (*Ac)[BT] = As[kc & 1];
        const float (*Bc)[BT] = Bs[kc & 1];
#pragma unroll
        for (int kk = 0; kk < KB; kk++) {
            float4 a0 = *(const float4*)&Ac[kk][ty * 8];
            float4 a1 = *(const float4*)&Ac[kk][ty * 8 + 4];
            ulonglong2 b0 = *(const ulonglong2*)&Bc[kk][tx * 8];
            ulonglong2 b1 = *(const ulonglong2*)&Bc[kk][tx * 8 + 4];
            unsigned long long bp0 = b0.x, bp1 = b0.y, bp2 = b1.x, bp3 = b1.y;
            float av[8] = {a0.x, a0.y, a0.z, a0.w, a1.x, a1.y, a1.z, a1.w};
#pragma unroll
            for (int i = 0; i < 8; i++) {
                unsigned long long ai = dup2(av[i]);
                ffma2(acc[i][0], ai, bp0);
                ffma2(acc[i][1], ai, bp1);
                ffma2(acc[i][2], ai, bp2);
                ffma2(acc[i][3], ai, bp3);
            }
        }
        __syncthreads();
    }

    // Transposed split write: Yt[b][m][c] hi/lo bf16.
#pragma unroll
    for (int jj = 0; jj < 8; jj++) {
        uint32_t hw[4], lw[4];
#pragma unroll
        for (int p = 0; p < 4; p++) {
            float v0 = (jj & 1) ? hi32(acc[2 * p][jj >> 1])     : lo32(acc[2 * p][jj >> 1]);
            float v1 = (jj & 1) ? hi32(acc[2 * p + 1][jj >> 1]) : lo32(acc[2 * p + 1][jj >> 1]);
            unsigned short h0 = f2bf(v0), h1 = f2bf(v1);
            unsigned short l0 = f2bf(v0 - bf2f(h0)), l1 = f2bf(v1 - bf2f(h1));
            hw[p] = (uint32_t)h0 | ((uint32_t)h1 << 16);
            lw[p] = (uint32_t)l0 | ((uint32_t)l1 << 16);
        }
        size_t row = (size_t)b * NDIM + (m0 + tx * 8 + jj);
        uint4* dh = (uint4*)(g_Yhi + row * CDIM + c0 + ty * 8);
        uint4* dl = (uint4*)(g_Ylo + row * CDIM + c0 + ty * 8);
        *dh = make_uint4(hw[0], hw[1], hw[2], hw[3]);
        *dl = make_uint4(lw[0], lw[1], lw[2], lw[3]);
    }
}

// ---------------- kernel C: mma.sync flash row-stats, m64 split-phase double buffer ----------------
// SMEM: Ahi[128][512B] @0 (64KB), Alo @65536 (64KB),
//       BH buf @131072 (64 rows x 512B = 32KB), BL buf @163840 (32KB),
//       sdiag @196608 (512B), sfac @197120 (512B). Total 197632.
#define SM_ALO   65536u
#define SM_BH    131072u
#define SM_BL    163840u
#define SM_SDIAG 196608u
#define SM_SFAC  197120u
#define SMEM_SZ  197632

__device__ __forceinline__ uint32_t a_addr(uint32_t sb, int comp, int row, int kc, int L) {
    int r = row + (L & 15);
    int kh = (L >> 4) & 1;
    return sb + (uint32_t)comp * SM_ALO + (uint32_t)(r * 512 + ((kc ^ (r & 7)) * 32) + kh * 16);
}
__device__ __forceinline__ uint32_t b_addr(uint32_t sb, uint32_t base, int p, int kc, int L) {
    int r = p * 16 + (L & 7) + (((L >> 4) & 1) << 3);
    int kh = (L >> 3) & 1;
    return sb + base + (uint32_t)(r * 512 + ((kc ^ (r & 7)) * 32) + kh * 16);
}

// cooperative load of one 64-row B component tile into swizzled smem
__device__ __forceinline__ void load_btile(uint32_t sb, uint32_t base,
                                           const __nv_bfloat16* __restrict__ Ysrc,
                                           int b, int t, int tid) {
    const __nv_bfloat16* rowp = Ysrc + ((size_t)b * NDIM + t * 64) * CDIM;
    for (int i = tid; i < 2048; i += 128) {
        int r = i >> 5, u = i & 31;
        cp16(sb + base + (uint32_t)(r * 512 + (((u >> 1) ^ (r & 7)) * 32) + (u & 1) * 16),
             rowp + (size_t)r * CDIM + u * 8);
    }
}

__global__ __launch_bounds__(128, 1) void attn_kernel(const float* __restrict__ X,
                                                      float* __restrict__ out) {
    extern __shared__ __align__(1024) char smem[];
    const uint32_t sb = smem_u32(smem);
    const int tid = threadIdx.x;
    const int L = tid & 31;
    const int w = tid >> 5;           // 0..3, all compute
    const int b  = blockIdx.y;
    const int n0 = blockIdx.x * 128;

    const float* Xb = X + (size_t)b * CDIM * NDIM;
    float* sdiag = (float*)(smem + SM_SDIAG);
    float* sfac  = (float*)(smem + SM_SFAC);

    // ---- prologue: stage A (Xt hi/lo) + BH_0; then BL_0 ----
    for (int i = tid; i < 8192; i += 128) {
        int comp = i >> 12;
        int rem = i & 4095;
        int r = rem >> 5, u = rem & 31;
        const __nv_bfloat16* src =
            (comp ? g_Xlo : g_Xhi) + ((size_t)b * NDIM + n0 + r) * CDIM + u * 8;
        uint32_t dst = sb + (uint32_t)comp * SM_ALO +
                       (uint32_t)(r * 512 + (((u >> 1) ^ (r & 7)) * 32) + (u & 1) * 16);
        cp16(dst, src);
    }
    load_btile(sb, SM_BH, g_Yhi, b, 0, tid);
    cp_commit();                         // group {A, BH0}
    load_btile(sb, SM_BL, g_Ylo, b, 0, tid);
    cp_commit();                         // group {BL0}
    cp_wait1();                          // A + BH0 landed (BL0 pending)
    __syncthreads();

    const int NT = NDIM / 64;            // 64 m-tiles
    const int diag_t = blockIdx.x * 2 + (w >> 1);

    float mrun[4], srun[4];
#pragma unroll
    for (int j = 0; j < 4; j++) { mrun[j] = -1e30f; srun[j] = 0.f; }

#pragma unroll 1
    for (int t = 0; t < NT; t++) {
        float acc[2][8][4];
#pragma unroll
        for (int a = 0; a < 2; a++)
#pragma unroll
            for (int bt = 0; bt < 8; bt++)
#pragma unroll
                for (int q = 0; q < 4; q++) acc[a][bt][q] = 0.f;

        // ---- phase 1: chains AH*BH + AL*BH (32 mma/kc) ----
#pragma unroll 2
        for (int kc = 0; kc < 16; kc++) {
            uint32_t AH[2][4], AL[2][4], BH[4][4];
            ldsm4(AH[0], a_addr(sb, 0, w * 32,      kc, L));
            ldsm4(AH[1], a_addr(sb, 0, w * 32 + 16, kc, L));
            ldsm4(AL[0], a_addr(sb, 1, w * 32,      kc, L));
            ldsm4(AL[1], a_addr(sb, 1, w * 32 + 16, kc, L));
#pragma unroll
            for (int p = 0; p < 4; p++) ldsm4(BH[p], b_addr(sb, SM_BH, p, kc, L));
#pragma unroll
            for (int a = 0; a < 2; a++)
#pragma unroll
                for (int bt = 0; bt < 8; bt++)
                    mma_bf16(acc[a][bt], AH[a], &BH[bt >> 1][(bt & 1) * 2]);
#pragma unroll
            for (int a = 0; a < 2; a++)
#pragma unroll
                for (int bt = 0; bt < 8; bt++)
                    mma_bf16(acc[a][bt], AL[a], &BH[bt >> 1][(bt & 1) * 2]);
        }
        __syncthreads();                         // all done reading BH buf
        if (t + 1 < NT) {
            load_btile(sb, SM_BH, g_Yhi, b, t + 1, tid);
            cp_commit();                         // pending {BL_t, BH_{t+1}}
            cp_wait1();                          // BL_t landed
        } else {
            cp_wait0();                          // BL_t landed
        }
        __syncthreads();                         // BL_t visible to all

        // ---- phase 2: chain AH*BL (16 mma/kc) ----
#pragma unroll 2
        for (int kc = 0; kc < 16; kc++) {
            uint32_t AH[2][4], BL[4][4];
            ldsm4(AH[0], a_addr(sb, 0, w * 32,      kc, L));
            ldsm4(AH[1], a_addr(sb, 0, w * 32 + 16, kc, L));
#pragma unroll
            for (int p = 0; p < 4; p++) ldsm4(BL[p], b_addr(sb, SM_BL, p, kc, L));
#pragma unroll
            for (int a = 0; a < 2; a++)
#pragma unroll
                for (int bt = 0; bt < 8; bt++)
                    mma_bf16(acc[a][bt], AH[a], &BL[bt >> 1][(bt & 1) * 2]);
        }

        // ---- diag extraction (tile covering this warp's rows) ----
        if (t == diag_t) {
#pragma unroll
            for (int a = 0; a < 2; a++)
#pragma unroll
                for (int h = 0; h < 2; h++) {
                    int btd = ((w & 1) << 2) + a * 2 + h;
                    int rn = a * 16 + h * 8 + (L >> 2);
                    if (2 * (L & 3) == (L >> 2))     sdiag[w * 32 + rn] = acc[a][btd][2 * h];
                    if (2 * (L & 3) + 1 == (L >> 2)) sdiag[w * 32 + rn] = acc[a][btd][2 * h + 1];
                }
        }

        // ---- online softmax: 4 rows x 16 cols per lane ----
#pragma unroll
        for (int a = 0; a < 2; a++)
#pragma unroll
            for (int h = 0; h < 2; h++) {
                const int j = 2 * a + h;
                float mx = -1e30f;
#pragma unroll
                for (int bt = 0; bt < 8; bt++) {
                    mx = fmaxf(mx, fmaxf(acc[a][bt][2 * h], acc[a][bt][2 * h + 1]));
                }
                float mnew = fmaxf(mrun[j], mx);
                float ss = 0.f;
#pragma unroll
                for (int bt = 0; bt < 8; bt++) {
                    ss += __expf(acc[a][bt][2 * h] - mnew);
                    ss += __expf(acc[a][bt][2 * h + 1] - mnew);
                }
                srun[j] = srun[j] * __expf(mrun[j] - mnew) + ss;
                mrun[j] = mnew;
            }

        __syncthreads();                         // all done reading BL buf
        if (t + 1 < NT) {
            load_btile(sb, SM_BL, g_Ylo, b, t + 1, tid);
            cp_commit();                         // pending {BH_{t+1}, BL_{t+1}}
            cp_wait1();                          // BH_{t+1} landed
        }
        __syncthreads();                         // BH_{t+1} visible (top barrier)
    }

    // ---- merge across the 4 lanes sharing each row; write sfac ----
#pragma unroll
    for (int j = 0; j < 4; j++) {
        const int a = j >> 1, h = j & 1;
        float m = mrun[j], sv = srun[j];
#pragma unroll
        for (int d = 1; d < 4; d <<= 1) {
            float mo = __shfl_xor_sync(0xffffffffu, m, d);
            float so = __shfl_xor_sync(0xffffffffu, sv, d);
            float mn = fmaxf(m, mo);
            sv = sv * __expf(m - mn) + so * __expf(mo - mn);
            m = mn;
        }
        if ((L & 3) == 0) {
            int nl = w * 32 + a * 16 + h * 8 + (L >> 2);
            sfac[nl] = __expf(sdiag[nl] - m) / sv;
        }
    }
    __syncthreads();

    // ---- store: out[c][n] = X[c][n] * fac[n] ----
    float* Ob = out + (size_t)b * CDIM * NDIM;
#pragma unroll 1
    for (int idx = tid; idx < 256 * 32; idx += 128) {
        int c = idx >> 5, g = idx & 31;
        float4 f = *(const float4*)&sfac[g * 4];
        float4 x = *(const float4*)(Xb + (size_t)c * NDIM + n0 + g * 4);
        x.x *= f.x; x.y *= f.y; x.z *= f.z; x.w *= f.w;
        *(float4*)(Ob + (size_t)c * NDIM + n0 + g * 4) = x;
    }
}

// ---------------- launch ----------------
extern "C" void kernel_launch(void* const* d_in, const int* in_sizes, int n_in,
                              void* d_out, int out_size) {
    const float* pts = (const float*)d_in[0];
    const float* Wq  = (const float*)d_in[1];
    const float* Wk  = (const float*)d_in[2];
    float* out = (float*)d_out;

    cudaFuncSetAttribute(attn_kernel, cudaFuncAttributeMaxDynamicSharedMemorySize, SMEM_SZ);

    mt_kernel<<<dim3(16, 16), dim3(16, 16)>>>(Wq, Wk);
    xt_kernel<<<dim3(NDIM / 32, CDIM / 32, BDIM), dim3(32, 8)>>>(pts);
    ymat_kernel<<<dim3(NDIM / BT, CDIM / BT, BDIM), 256>>>(pts);
    attn_kernel<<<dim3(NDIM / 128, BDIM), 128, SMEM_SZ>>>(pts, out);
}